// round 1
// baseline (speedup 1.0000x reference)
#include <cuda_runtime.h>
#include <math.h>

#define BB 8
#define TT 769
#define CC 1024
#define HH 16
#define HD 64
#define LL 32
#define COND 256
#define MROWS (BB*TT)   // 6152
#define SCALE 0.125f    // 1/sqrt(64)

// Scratch buffers (allocation-free requirement -> device globals)
__device__ float g_Q[(size_t)MROWS * CC];
__device__ float g_K[(size_t)MROWS * CC];
__device__ float g_V[(size_t)MROWS * CC];
__device__ float g_ATT[(size_t)MROWS * CC];

// ---------------------------------------------------------------------------
// NT GEMM + bias: Y[m,n] = sum_k X[m,k] * W[n,k] + bias[n]
// X: [M,1024] row-major, W: [1024,1024] row-major. Tile 128x128x16, 256 thr,
// 8x8 per-thread microtile in 4+64 split for conflict-free smem float4 reads.
// ---------------------------------------------------------------------------
__global__ void __launch_bounds__(256) gemm_bias_kernel(
    const float* __restrict__ X, const float* __restrict__ W,
    const float* __restrict__ bias, float* __restrict__ Y, int M)
{
    const int N = CC, K = CC;
    __shared__ float As[16][128];
    __shared__ float Bs[16][128];

    const int tid = threadIdx.x;
    const int tx = tid & 15, ty = tid >> 4;
    const int bm = blockIdx.y * 128, bn = blockIdx.x * 128;

    float acc[8][8];
#pragma unroll
    for (int i = 0; i < 8; i++)
#pragma unroll
        for (int j = 0; j < 8; j++) acc[i][j] = 0.f;

    for (int k0 = 0; k0 < K; k0 += 16) {
#pragma unroll
        for (int i = 0; i < 2; i++) {
            int f = tid * 2 + i;          // 0..511
            int r = f >> 2;
            int c4 = (f & 3) * 4;
            int gr = bm + r;
            float4 v = make_float4(0.f, 0.f, 0.f, 0.f);
            if (gr < M) v = *(const float4*)(X + (size_t)gr * K + k0 + c4);
            As[c4 + 0][r] = v.x; As[c4 + 1][r] = v.y;
            As[c4 + 2][r] = v.z; As[c4 + 3][r] = v.w;
            float4 w = *(const float4*)(W + (size_t)(bn + r) * K + k0 + c4);
            Bs[c4 + 0][r] = w.x; Bs[c4 + 1][r] = w.y;
            Bs[c4 + 2][r] = w.z; Bs[c4 + 3][r] = w.w;
        }
        __syncthreads();

#pragma unroll
        for (int kk = 0; kk < 16; kk++) {
            float4 a0 = *(const float4*)&As[kk][ty * 4];
            float4 a1 = *(const float4*)&As[kk][64 + ty * 4];
            float4 b0 = *(const float4*)&Bs[kk][tx * 4];
            float4 b1 = *(const float4*)&Bs[kk][64 + tx * 4];
            float a[8] = {a0.x, a0.y, a0.z, a0.w, a1.x, a1.y, a1.z, a1.w};
            float b[8] = {b0.x, b0.y, b0.z, b0.w, b1.x, b1.y, b1.z, b1.w};
#pragma unroll
            for (int i = 0; i < 8; i++)
#pragma unroll
                for (int j = 0; j < 8; j++) acc[i][j] += a[i] * b[j];
        }
        __syncthreads();
    }

#pragma unroll
    for (int i = 0; i < 8; i++) {
        int r = bm + ((i < 4) ? (ty * 4 + i) : (64 + ty * 4 + (i - 4)));
        if (r >= M) continue;
#pragma unroll
        for (int jh = 0; jh < 2; jh++) {
            int c = bn + jh * 64 + tx * 4;
            float4 o;
            o.x = acc[i][jh * 4 + 0] + bias[c + 0];
            o.y = acc[i][jh * 4 + 1] + bias[c + 1];
            o.z = acc[i][jh * 4 + 2] + bias[c + 2];
            o.w = acc[i][jh * 4 + 3] + bias[c + 3];
            *(float4*)(Y + (size_t)r * N + c) = o;
        }
    }
}

// ---------------------------------------------------------------------------
// Rotary on first LL dims of each head of Q and K, in place.
// out[2i]   = x[2i]*cos(f[2i])   - x[2i+1]*sin(f[2i])
// out[2i+1] = x[2i+1]*cos(f[2i+1]) + x[2i]*sin(f[2i+1])
// ---------------------------------------------------------------------------
__global__ void rotary_kernel(float* __restrict__ Q, float* __restrict__ Kb,
                              const float* __restrict__ rope)
{
    const int NP = BB * TT * HH * (LL / 2);   // 1,574,912
    int idx = blockIdx.x * blockDim.x + threadIdx.x;
    if (idx >= NP) return;
    int i = idx & 15;            // pair index within head
    int h = (idx >> 4) & 15;
    int t = (idx >> 8) % TT;
    int b = idx / (256 * TT);
    int d0 = 2 * i;
    size_t base = ((size_t)(b * TT + t)) * CC + h * HD;
    float f0 = rope[t * LL + d0];
    float f1 = rope[t * LL + d0 + 1];
    float c0 = cosf(f0), s0 = sinf(f0);
    float c1 = cosf(f1), s1 = sinf(f1);

    float q0 = Q[base + d0], q1 = Q[base + d0 + 1];
    Q[base + d0]     = q0 * c0 - q1 * s0;
    Q[base + d0 + 1] = q1 * c1 + q0 * s1;

    float k0 = Kb[base + d0], k1 = Kb[base + d0 + 1];
    Kb[base + d0]     = k0 * c0 - k1 * s0;
    Kb[base + d0 + 1] = k1 * c1 + k0 * s1;
}

// ---------------------------------------------------------------------------
// Flash attention, fp32. One CTA = (b, h, 64-query tile). 256 threads (16x16),
// each owns a 4x4 microtile of S/O. K stored d-major (stride 68) in smem so
// the QK^T inner loop reads are conflict-free float4s; P (exp'd scores)
// overwrites the K buffer. Mask: col < COND + row (and col < T).
// ---------------------------------------------------------------------------
__device__ __forceinline__ float redmax16(float v) {
#pragma unroll
    for (int off = 8; off >= 1; off >>= 1)
        v = fmaxf(v, __shfl_xor_sync(0xffffffffu, v, off));
    return v;
}
__device__ __forceinline__ float redsum16(float v) {
#pragma unroll
    for (int off = 8; off >= 1; off >>= 1)
        v += __shfl_xor_sync(0xffffffffu, v, off);
    return v;
}

__global__ void __launch_bounds__(256) attn_kernel(
    const float* __restrict__ Q, const float* __restrict__ Kg,
    const float* __restrict__ Vg, float* __restrict__ O)
{
    extern __shared__ float sm[];
    float* Qst = sm;                 // [64 d][68] transposed Q tile (d-major)
    float* Kst = Qst + 64 * 68;      // [64 d][68] transposed K tile; aliased as Ps[64 r][68]
    float* Vs  = Kst + 64 * 68;      // [64 c][64]
    float* Ps  = Kst;                // alias

    const int tid = threadIdx.x;
    const int tx = tid & 15, ty = tid >> 4;
    const int qt = blockIdx.x, h = blockIdx.y, b = blockIdx.z;
    const int q0 = qt * 64;
    const size_t rowbase = (size_t)b * TT * CC + (size_t)h * HD;

    // Load Q tile transposed: Qst[d][r] = Q[q0+r][d]
#pragma unroll
    for (int i = 0; i < 4; i++) {
        int f = tid + i * 256;       // 0..1023
        int r = f >> 4, d4 = (f & 15) * 4;
        int qg = q0 + r;
        float4 v = make_float4(0.f, 0.f, 0.f, 0.f);
        if (qg < TT) v = *(const float4*)(Q + rowbase + (size_t)qg * CC + d4);
        Qst[(d4 + 0) * 68 + r] = v.x;
        Qst[(d4 + 1) * 68 + r] = v.y;
        Qst[(d4 + 2) * 68 + r] = v.z;
        Qst[(d4 + 3) * 68 + r] = v.w;
    }

    float m_i[4], l_i[4], o[4][4];
#pragma unroll
    for (int i = 0; i < 4; i++) {
        m_i[i] = -1e30f; l_i[i] = 0.f;
#pragma unroll
        for (int j = 0; j < 4; j++) o[i][j] = 0.f;
    }

    int kv_end = q0 + COND + 63;     // exclusive: max col+1 = 256 + (q0+63)
    if (kv_end > TT) kv_end = TT;

    for (int kv0 = 0; kv0 < kv_end; kv0 += 64) {
        __syncthreads();             // prev PV reads done; Qst visible (iter 0)

        // Load K transposed + V
#pragma unroll
        for (int i = 0; i < 4; i++) {
            int f = tid + i * 256;
            int c = f >> 4, d4 = (f & 15) * 4;
            int kg = kv0 + c;
            float4 kv = make_float4(0.f, 0.f, 0.f, 0.f);
            float4 vv = make_float4(0.f, 0.f, 0.f, 0.f);
            if (kg < TT) {
                kv = *(const float4*)(Kg + rowbase + (size_t)kg * CC + d4);
                vv = *(const float4*)(Vg + rowbase + (size_t)kg * CC + d4);
            }
            Kst[(d4 + 0) * 68 + c] = kv.x;
            Kst[(d4 + 1) * 68 + c] = kv.y;
            Kst[(d4 + 2) * 68 + c] = kv.z;
            Kst[(d4 + 3) * 68 + c] = kv.w;
            *(float4*)&Vs[c * 64 + d4] = vv;
        }
        __syncthreads();

        // S = Q K^T  (rows ty*4.., cols tx*4..)
        float s[4][4];
#pragma unroll
        for (int i = 0; i < 4; i++)
#pragma unroll
            for (int j = 0; j < 4; j++) s[i][j] = 0.f;

#pragma unroll 8
        for (int dd = 0; dd < 64; dd++) {
            float4 a4 = *(const float4*)&Qst[dd * 68 + ty * 4];
            float4 b4 = *(const float4*)&Kst[dd * 68 + tx * 4];
            float a[4] = {a4.x, a4.y, a4.z, a4.w};
            float bb[4] = {b4.x, b4.y, b4.z, b4.w};
#pragma unroll
            for (int i = 0; i < 4; i++)
#pragma unroll
                for (int j = 0; j < 4; j++) s[i][j] += a[i] * bb[j];
        }

        // Mask + online softmax (per row; all 16 tx lanes converge via shuffles)
#pragma unroll
        for (int i = 0; i < 4; i++) {
            int qg = q0 + ty * 4 + i;
            float rmax = -1e30f;
#pragma unroll
            for (int j = 0; j < 4; j++) {
                int kg = kv0 + tx * 4 + j;
                bool ok = (kg < COND + qg) && (kg < TT);
                s[i][j] = ok ? s[i][j] * SCALE : -1e30f;
                rmax = fmaxf(rmax, s[i][j]);
            }
            rmax = redmax16(rmax);
            float mn = fmaxf(m_i[i], rmax);
            float al = __expf(m_i[i] - mn);
            float rs = 0.f;
#pragma unroll
            for (int j = 0; j < 4; j++) {
                s[i][j] = __expf(s[i][j] - mn);
                rs += s[i][j];
            }
            rs = redsum16(rs);
            l_i[i] = l_i[i] * al + rs;
            m_i[i] = mn;
#pragma unroll
            for (int j = 0; j < 4; j++) o[i][j] *= al;
        }

        __syncthreads();             // all S reads of Kst done before P overwrite
#pragma unroll
        for (int i = 0; i < 4; i++) {
            *(float4*)&Ps[(ty * 4 + i) * 68 + tx * 4] =
                make_float4(s[i][0], s[i][1], s[i][2], s[i][3]);
        }
        __syncthreads();

        // O += P V   (thread: rows ty*4.., out dims tx*4..)
#pragma unroll 8
        for (int c = 0; c < 64; c++) {
            float4 v4 = *(const float4*)&Vs[c * 64 + tx * 4];
            float p0 = Ps[(ty * 4 + 0) * 68 + c];
            float p1 = Ps[(ty * 4 + 1) * 68 + c];
            float p2 = Ps[(ty * 4 + 2) * 68 + c];
            float p3 = Ps[(ty * 4 + 3) * 68 + c];
            o[0][0] += p0 * v4.x; o[0][1] += p0 * v4.y; o[0][2] += p0 * v4.z; o[0][3] += p0 * v4.w;
            o[1][0] += p1 * v4.x; o[1][1] += p1 * v4.y; o[1][2] += p1 * v4.z; o[1][3] += p1 * v4.w;
            o[2][0] += p2 * v4.x; o[2][1] += p2 * v4.y; o[2][2] += p2 * v4.z; o[2][3] += p2 * v4.w;
            o[3][0] += p3 * v4.x; o[3][1] += p3 * v4.y; o[3][2] += p3 * v4.z; o[3][3] += p3 * v4.w;
        }
    }

    // Normalize + store
#pragma unroll
    for (int i = 0; i < 4; i++) {
        int qg = q0 + ty * 4 + i;
        if (qg >= TT) continue;
        float inv = 1.0f / l_i[i];
        float4 out;
        out.x = o[i][0] * inv; out.y = o[i][1] * inv;
        out.z = o[i][2] * inv; out.w = o[i][3] * inv;
        *(float4*)(O + rowbase + (size_t)qg * CC + tx * 4) = out;
    }
}

// ---------------------------------------------------------------------------
// Launch
// ---------------------------------------------------------------------------
extern "C" void kernel_launch(void* const* d_in, const int* in_sizes, int n_in,
                              void* d_out, int out_size)
{
    const float* x_q  = (const float*)d_in[0];
    const float* x_kv = (const float*)d_in[1];
    const float* rope = (const float*)d_in[2];
    const float* Wq   = (const float*)d_in[3];
    const float* bq   = (const float*)d_in[4];
    const float* Wk   = (const float*)d_in[5];
    const float* bk   = (const float*)d_in[6];
    const float* Wv   = (const float*)d_in[7];
    const float* bv   = (const float*)d_in[8];
    const float* Wp   = (const float*)d_in[9];
    const float* bp   = (const float*)d_in[10];
    float* out = (float*)d_out;

    float *q, *k, *v, *att;
    cudaGetSymbolAddress((void**)&q,   g_Q);
    cudaGetSymbolAddress((void**)&k,   g_K);
    cudaGetSymbolAddress((void**)&v,   g_V);
    cudaGetSymbolAddress((void**)&att, g_ATT);

    dim3 gemm_grid(CC / 128, (MROWS + 127) / 128);   // (8, 49)

    gemm_bias_kernel<<<gemm_grid, 256>>>(x_q,  Wq, bq, q, MROWS);
    gemm_bias_kernel<<<gemm_grid, 256>>>(x_kv, Wk, bk, k, MROWS);
    gemm_bias_kernel<<<gemm_grid, 256>>>(x_kv, Wv, bv, v, MROWS);

    int npairs = BB * TT * HH * (LL / 2);
    rotary_kernel<<<(npairs + 255) / 256, 256>>>(q, k, rope);

    int smem = (64 * 68 + 64 * 68 + 64 * 64) * (int)sizeof(float);  // 51200 B
    cudaFuncSetAttribute(attn_kernel, cudaFuncAttributeMaxDynamicSharedMemorySize, smem);
    dim3 attn_grid((TT + 63) / 64, HH, BB);          // (13, 16, 8)
    attn_kernel<<<attn_grid, 256, smem>>>(q, k, v, att);

    gemm_bias_kernel<<<gemm_grid, 256>>>(att, Wp, bp, out, MROWS);
}

// round 3
// speedup vs baseline: 1.7128x; 1.7128x over previous
#include <cuda_runtime.h>
#include <cuda_bf16.h>
#include <math.h>
#include <stdint.h>

#define BB 8
#define TT 769
#define CC 1024
#define HH 16
#define HD 64
#define LL 32
#define COND 256
#define MROWS (BB*TT)   // 6152
#define SCALE 0.125f

// Scratch buffers (allocation-free requirement -> device globals)
__device__ float g_Q[(size_t)MROWS * CC];
__device__ float g_K[(size_t)MROWS * CC];
__device__ float g_V[(size_t)MROWS * CC];
__device__ float g_ATT[(size_t)MROWS * CC];

// ===========================================================================
// Helpers
// ===========================================================================
__device__ __forceinline__ uint32_t smem_to_u32(const void* p) {
    uint32_t a;
    asm("{ .reg .u64 t; cvta.to.shared.u64 t, %1; cvt.u32.u64 %0, t; }"
        : "=r"(a) : "l"(p));
    return a;
}

__device__ __forceinline__ void ldm_x4(uint32_t* r, uint32_t addr) {
    asm volatile("ldmatrix.sync.aligned.m8n8.x4.shared.b16 {%0,%1,%2,%3}, [%4];"
        : "=r"(r[0]), "=r"(r[1]), "=r"(r[2]), "=r"(r[3]) : "r"(addr));
}

__device__ __forceinline__ void mma16816(float* d, const uint32_t* a,
                                         uint32_t b0, uint32_t b1) {
    asm volatile(
        "mma.sync.aligned.m16n8k16.row.col.f32.bf16.bf16.f32 "
        "{%0,%1,%2,%3}, {%4,%5,%6,%7}, {%8,%9}, {%0,%1,%2,%3};"
        : "+f"(d[0]), "+f"(d[1]), "+f"(d[2]), "+f"(d[3])
        : "r"(a[0]), "r"(a[1]), "r"(a[2]), "r"(a[3]), "r"(b0), "r"(b1));
}

__device__ __forceinline__ uint32_t packbf(float a, float b) {
    __nv_bfloat162 t = __floats2bfloat162_rn(a, b);
    return *reinterpret_cast<uint32_t*>(&t);
}

// Split float4 into hi/lo bf16x4 (8B each), store to smem.
__device__ __forceinline__ void split_store(float4 v, char* hip, char* lop) {
    __nv_bfloat16 h0 = __float2bfloat16(v.x);
    __nv_bfloat16 h1 = __float2bfloat16(v.y);
    __nv_bfloat16 h2 = __float2bfloat16(v.z);
    __nv_bfloat16 h3 = __float2bfloat16(v.w);
    float r0 = v.x - __bfloat162float(h0);
    float r1 = v.y - __bfloat162float(h1);
    float r2 = v.z - __bfloat162float(h2);
    float r3 = v.w - __bfloat162float(h3);
    uint2 hv, lv;
    hv.x = packbf(__bfloat162float(h0), __bfloat162float(h1));
    hv.y = packbf(__bfloat162float(h2), __bfloat162float(h3));
    lv.x = packbf(r0, r1);
    lv.y = packbf(r2, r3);
    *reinterpret_cast<uint2*>(hip) = hv;
    *reinterpret_cast<uint2*>(lop) = lv;
}

// ===========================================================================
// bf16-split tensor-core NT GEMM + bias: Y[m,n] = sum_k X[m,k]*W[n,k] + b[n]
// CTA tile 128x128x32. 8 warps (2M x 4N), warp tile 64x32.
// smem rows are 80 bytes (40 bf16) -> ldmatrix conflict-free (5r mod 8 perm).
// blockIdx.z selects one of three (X, W, bias, Y) tuples.
// ===========================================================================
#define RSB 80            // smem row stride, bytes
#define SM_A_HI 0
#define SM_A_LO 10240
#define SM_B_HI 20480
#define SM_B_LO 30720

__global__ void __launch_bounds__(256) gemm_tc_kernel(
    const float* __restrict__ X0, const float* __restrict__ W0,
    const float* __restrict__ B0, float* __restrict__ Y0,
    const float* __restrict__ X1, const float* __restrict__ W1,
    const float* __restrict__ B1, float* __restrict__ Y1,
    const float* __restrict__ X2, const float* __restrict__ W2,
    const float* __restrict__ B2, float* __restrict__ Y2,
    int M)
{
    __shared__ __align__(16) char sm[40960];

    const int tid = threadIdx.x;
    const int lid = tid & 31;
    const int wid = tid >> 5;
    const int wm = wid >> 2;        // 0..1
    const int wn = wid & 3;         // 0..3

    const float *X, *W, *Bi;
    float* Y;
    if (blockIdx.z == 0)      { X = X0; W = W0; Bi = B0; Y = Y0; }
    else if (blockIdx.z == 1) { X = X1; W = W1; Bi = B1; Y = Y1; }
    else                      { X = X2; W = W2; Bi = B2; Y = Y2; }

    const int bm = blockIdx.y * 128, bn = blockIdx.x * 128;

    const uint32_t smb = smem_to_u32(sm);
    // per-lane ldmatrix offset: row (l&15), 16B-half (l>>4)
    const uint32_t lmoff = (uint32_t)((lid & 15) * RSB + ((lid >> 4) << 4));

    float acc[4][4][4];
#pragma unroll
    for (int a = 0; a < 4; a++)
#pragma unroll
        for (int b = 0; b < 4; b++)
#pragma unroll
            for (int c = 0; c < 4; c++) acc[a][b][c] = 0.f;

    // Global-load staging (row/col derived from f = i*256 + tid)
    float4 xr[4], wr[4];
#pragma unroll
    for (int i = 0; i < 4; i++) {
        int f = i * 256 + tid;
        int row = f >> 3, c4 = (f & 7) << 2;
        xr[i] = make_float4(0.f, 0.f, 0.f, 0.f);
        if (bm + row < M)
            xr[i] = *(const float4*)(X + (size_t)(bm + row) * CC + c4);
        wr[i] = *(const float4*)(W + (size_t)(bn + row) * CC + c4);
    }

    for (int ch = 0; ch < 32; ch++) {
        // Store staged chunk to smem (hi/lo split)
#pragma unroll
        for (int i = 0; i < 4; i++) {
            int f = i * 256 + tid;
            int row = f >> 3, c4 = (f & 7) << 2;
            uint32_t off = (uint32_t)(row * RSB + c4 * 2);
            split_store(xr[i], sm + SM_A_HI + off, sm + SM_A_LO + off);
            split_store(wr[i], sm + SM_B_HI + off, sm + SM_B_LO + off);
        }
        __syncthreads();

        // Prefetch next chunk (LDGs overlap the MMA phase below)
        if (ch < 31) {
            int k0 = (ch + 1) * 32;
#pragma unroll
            for (int i = 0; i < 4; i++) {
                int f = i * 256 + tid;
                int row = f >> 3, c4 = (f & 7) << 2;
                xr[i] = make_float4(0.f, 0.f, 0.f, 0.f);
                if (bm + row < M)
                    xr[i] = *(const float4*)(X + (size_t)(bm + row) * CC + k0 + c4);
                wr[i] = *(const float4*)(W + (size_t)(bn + row) * CC + k0 + c4);
            }
        }

        // MMA phase: 2 k-steps of 16
#pragma unroll
        for (int ks = 0; ks < 2; ks++) {
            const uint32_t kofs = (uint32_t)(ks * 32);
            uint32_t Ah[4][4], Al[4][4], Bf[2][4];

#pragma unroll
            for (int mt = 0; mt < 4; mt++) {
                uint32_t rb = (uint32_t)((wm * 64 + mt * 16) * RSB) + kofs + lmoff;
                ldm_x4(Ah[mt], smb + SM_A_HI + rb);
                ldm_x4(Al[mt], smb + SM_A_LO + rb);
            }
            // B hi: Ah*Bh and Al*Bh
#pragma unroll
            for (int np = 0; np < 2; np++) {
                uint32_t rb = (uint32_t)((wn * 32 + np * 16) * RSB) + kofs + lmoff;
                ldm_x4(Bf[np], smb + SM_B_HI + rb);
            }
#pragma unroll
            for (int mt = 0; mt < 4; mt++)
#pragma unroll
                for (int nt = 0; nt < 4; nt++) {
                    uint32_t b0 = Bf[nt >> 1][nt & 1];
                    uint32_t b1 = Bf[nt >> 1][2 + (nt & 1)];
                    mma16816(acc[mt][nt], Ah[mt], b0, b1);
                    mma16816(acc[mt][nt], Al[mt], b0, b1);
                }
            // B lo: Ah*Bl (reuse Bf regs)
#pragma unroll
            for (int np = 0; np < 2; np++) {
                uint32_t rb = (uint32_t)((wn * 32 + np * 16) * RSB) + kofs + lmoff;
                ldm_x4(Bf[np], smb + SM_B_LO + rb);
            }
#pragma unroll
            for (int mt = 0; mt < 4; mt++)
#pragma unroll
                for (int nt = 0; nt < 4; nt++) {
                    uint32_t b0 = Bf[nt >> 1][nt & 1];
                    uint32_t b1 = Bf[nt >> 1][2 + (nt & 1)];
                    mma16816(acc[mt][nt], Ah[mt], b0, b1);
                }
        }
        __syncthreads();
    }

    // Epilogue: frag layout -> global, + bias. Lane owns rows l/4, l/4+8,
    // cols 2*(l%4), 2*(l%4)+1 within each 16x8 tile.
    const int rbase = bm + wm * 64 + (lid >> 2);
    const int cbase = bn + wn * 32 + (lid & 3) * 2;
#pragma unroll
    for (int mt = 0; mt < 4; mt++) {
#pragma unroll
        for (int nt = 0; nt < 4; nt++) {
            int c = cbase + nt * 8;
            float2 bv = *(const float2*)(Bi + c);
            int r0 = rbase + mt * 16;
            int r1 = r0 + 8;
            if (r0 < M) {
                float2 o0 = make_float2(acc[mt][nt][0] + bv.x, acc[mt][nt][1] + bv.y);
                *(float2*)(Y + (size_t)r0 * CC + c) = o0;
            }
            if (r1 < M) {
                float2 o1 = make_float2(acc[mt][nt][2] + bv.x, acc[mt][nt][3] + bv.y);
                *(float2*)(Y + (size_t)r1 * CC + c) = o1;
            }
        }
    }
}

// ---------------------------------------------------------------------------
// Rotary on first LL dims of each head of Q and K, in place.
// ---------------------------------------------------------------------------
__global__ void rotary_kernel(float* __restrict__ Q, float* __restrict__ Kb,
                              const float* __restrict__ rope)
{
    const int NP = BB * TT * HH * (LL / 2);
    int idx = blockIdx.x * blockDim.x + threadIdx.x;
    if (idx >= NP) return;
    int i = idx & 15;
    int h = (idx >> 4) & 15;
    int t = (idx >> 8) % TT;
    int b = idx / (256 * TT);
    int d0 = 2 * i;
    size_t base = ((size_t)(b * TT + t)) * CC + h * HD;
    float f0 = rope[t * LL + d0];
    float f1 = rope[t * LL + d0 + 1];
    float c0 = cosf(f0), s0 = sinf(f0);
    float c1 = cosf(f1), s1 = sinf(f1);

    float q0 = Q[base + d0], q1 = Q[base + d0 + 1];
    Q[base + d0]     = q0 * c0 - q1 * s0;
    Q[base + d0 + 1] = q1 * c1 + q0 * s1;

    float k0 = Kb[base + d0], k1 = Kb[base + d0 + 1];
    Kb[base + d0]     = k0 * c0 - k1 * s0;
    Kb[base + d0 + 1] = k1 * c1 + k0 * s1;
}

// ---------------------------------------------------------------------------
// Flash attention, fp32 (unchanged from R1; already near FFMA roofline).
// ---------------------------------------------------------------------------
__device__ __forceinline__ float redmax16(float v) {
#pragma unroll
    for (int off = 8; off >= 1; off >>= 1)
        v = fmaxf(v, __shfl_xor_sync(0xffffffffu, v, off));
    return v;
}
__device__ __forceinline__ float redsum16(float v) {
#pragma unroll
    for (int off = 8; off >= 1; off >>= 1)
        v += __shfl_xor_sync(0xffffffffu, v, off);
    return v;
}

__global__ void __launch_bounds__(256) attn_kernel(
    const float* __restrict__ Q, const float* __restrict__ Kg,
    const float* __restrict__ Vg, float* __restrict__ O)
{
    extern __shared__ float smf[];
    float* Qst = smf;
    float* Kst = Qst + 64 * 68;
    float* Vs  = Kst + 64 * 68;
    float* Ps  = Kst;

    const int tid = threadIdx.x;
    const int tx = tid & 15, ty = tid >> 4;
    const int qt = blockIdx.x, h = blockIdx.y, b = blockIdx.z;
    const int q0 = qt * 64;
    const size_t rowbase = (size_t)b * TT * CC + (size_t)h * HD;

#pragma unroll
    for (int i = 0; i < 4; i++) {
        int f = tid + i * 256;
        int r = f >> 4, d4 = (f & 15) * 4;
        int qg = q0 + r;
        float4 v = make_float4(0.f, 0.f, 0.f, 0.f);
        if (qg < TT) v = *(const float4*)(Q + rowbase + (size_t)qg * CC + d4);
        Qst[(d4 + 0) * 68 + r] = v.x;
        Qst[(d4 + 1) * 68 + r] = v.y;
        Qst[(d4 + 2) * 68 + r] = v.z;
        Qst[(d4 + 3) * 68 + r] = v.w;
    }

    float m_i[4], l_i[4], o[4][4];
#pragma unroll
    for (int i = 0; i < 4; i++) {
        m_i[i] = -1e30f; l_i[i] = 0.f;
#pragma unroll
        for (int j = 0; j < 4; j++) o[i][j] = 0.f;
    }

    int kv_end = q0 + COND + 63;
    if (kv_end > TT) kv_end = TT;

    for (int kv0 = 0; kv0 < kv_end; kv0 += 64) {
        __syncthreads();

#pragma unroll
        for (int i = 0; i < 4; i++) {
            int f = tid + i * 256;
            int c = f >> 4, d4 = (f & 15) * 4;
            int kg = kv0 + c;
            float4 kv = make_float4(0.f, 0.f, 0.f, 0.f);
            float4 vv = make_float4(0.f, 0.f, 0.f, 0.f);
            if (kg < TT) {
                kv = *(const float4*)(Kg + rowbase + (size_t)kg * CC + d4);
                vv = *(const float4*)(Vg + rowbase + (size_t)kg * CC + d4);
            }
            Kst[(d4 + 0) * 68 + c] = kv.x;
            Kst[(d4 + 1) * 68 + c] = kv.y;
            Kst[(d4 + 2) * 68 + c] = kv.z;
            Kst[(d4 + 3) * 68 + c] = kv.w;
            *(float4*)&Vs[c * 64 + d4] = vv;
        }
        __syncthreads();

        float s[4][4];
#pragma unroll
        for (int i = 0; i < 4; i++)
#pragma unroll
            for (int j = 0; j < 4; j++) s[i][j] = 0.f;

#pragma unroll 8
        for (int dd = 0; dd < 64; dd++) {
            float4 a4 = *(const float4*)&Qst[dd * 68 + ty * 4];
            float4 b4 = *(const float4*)&Kst[dd * 68 + tx * 4];
            float a[4] = {a4.x, a4.y, a4.z, a4.w};
            float bb[4] = {b4.x, b4.y, b4.z, b4.w};
#pragma unroll
            for (int i = 0; i < 4; i++)
#pragma unroll
                for (int j = 0; j < 4; j++) s[i][j] += a[i] * bb[j];
        }

#pragma unroll
        for (int i = 0; i < 4; i++) {
            int qg = q0 + ty * 4 + i;
            float rmax = -1e30f;
#pragma unroll
            for (int j = 0; j < 4; j++) {
                int kg = kv0 + tx * 4 + j;
                bool ok = (kg < COND + qg) && (kg < TT);
                s[i][j] = ok ? s[i][j] * SCALE : -1e30f;
                rmax = fmaxf(rmax, s[i][j]);
            }
            rmax = redmax16(rmax);
            float mn = fmaxf(m_i[i], rmax);
            float al = __expf(m_i[i] - mn);
            float rs = 0.f;
#pragma unroll
            for (int j = 0; j < 4; j++) {
                s[i][j] = __expf(s[i][j] - mn);
                rs += s[i][j];
            }
            rs = redsum16(rs);
            l_i[i] = l_i[i] * al + rs;
            m_i[i] = mn;
#pragma unroll
            for (int j = 0; j < 4; j++) o[i][j] *= al;
        }

        __syncthreads();
#pragma unroll
        for (int i = 0; i < 4; i++) {
            *(float4*)&Ps[(ty * 4 + i) * 68 + tx * 4] =
                make_float4(s[i][0], s[i][1], s[i][2], s[i][3]);
        }
        __syncthreads();

#pragma unroll 8
        for (int c = 0; c < 64; c++) {
            float4 v4 = *(const float4*)&Vs[c * 64 + tx * 4];
            float p0 = Ps[(ty * 4 + 0) * 68 + c];
            float p1 = Ps[(ty * 4 + 1) * 68 + c];
            float p2 = Ps[(ty * 4 + 2) * 68 + c];
            float p3 = Ps[(ty * 4 + 3) * 68 + c];
            o[0][0] += p0 * v4.x; o[0][1] += p0 * v4.y; o[0][2] += p0 * v4.z; o[0][3] += p0 * v4.w;
            o[1][0] += p1 * v4.x; o[1][1] += p1 * v4.y; o[1][2] += p1 * v4.z; o[1][3] += p1 * v4.w;
            o[2][0] += p2 * v4.x; o[2][1] += p2 * v4.y; o[2][2] += p2 * v4.z; o[2][3] += p2 * v4.w;
            o[3][0] += p3 * v4.x; o[3][1] += p3 * v4.y; o[3][2] += p3 * v4.z; o[3][3] += p3 * v4.w;
        }
    }

#pragma unroll
    for (int i = 0; i < 4; i++) {
        int qg = q0 + ty * 4 + i;
        if (qg >= TT) continue;
        float inv = 1.0f / l_i[i];
        float4 out;
        out.x = o[i][0] * inv; out.y = o[i][1] * inv;
        out.z = o[i][2] * inv; out.w = o[i][3] * inv;
        *(float4*)(O + rowbase + (size_t)qg * CC + tx * 4) = out;
    }
}

// ---------------------------------------------------------------------------
// Launch
// ---------------------------------------------------------------------------
extern "C" void kernel_launch(void* const* d_in, const int* in_sizes, int n_in,
                              void* d_out, int out_size)
{
    const float* x_q  = (const float*)d_in[0];
    const float* x_kv = (const float*)d_in[1];
    const float* rope = (const float*)d_in[2];
    const float* Wq   = (const float*)d_in[3];
    const float* bq   = (const float*)d_in[4];
    const float* Wk   = (const float*)d_in[5];
    const float* bk   = (const float*)d_in[6];
    const float* Wv   = (const float*)d_in[7];
    const float* bv   = (const float*)d_in[8];
    const float* Wp   = (const float*)d_in[9];
    const float* bp   = (const float*)d_in[10];
    float* out = (float*)d_out;

    float *q, *k, *v, *att;
    cudaGetSymbolAddress((void**)&q,   g_Q);
    cudaGetSymbolAddress((void**)&k,   g_K);
    cudaGetSymbolAddress((void**)&v,   g_V);
    cudaGetSymbolAddress((void**)&att, g_ATT);

    // Fused Q/K/V projections: grid.z picks the tuple.
    dim3 g_qkv(CC / 128, (MROWS + 127) / 128, 3);   // (8, 49, 3)
    gemm_tc_kernel<<<g_qkv, 256>>>(
        x_q,  Wq, bq, q,
        x_kv, Wk, bk, k,
        x_kv, Wv, bv, v, MROWS);

    int npairs = BB * TT * HH * (LL / 2);
    rotary_kernel<<<(npairs + 255) / 256, 256>>>(q, k, rope);

    int smem = (64 * 68 + 64 * 68 + 64 * 64) * (int)sizeof(float);  // 51200 B
    cudaFuncSetAttribute(attn_kernel, cudaFuncAttributeMaxDynamicSharedMemorySize, smem);
    dim3 attn_grid((TT + 63) / 64, HH, BB);
    attn_kernel<<<attn_grid, 256, smem>>>(q, k, v, att);

    // Output projection (single tuple, grid.z = 1).
    dim3 g_out(CC / 128, (MROWS + 127) / 128, 1);
    gemm_tc_kernel<<<g_out, 256>>>(
        att, Wp, bp, out,
        att, Wp, bp, out,
        att, Wp, bp, out, MROWS);
}

// round 4
// speedup vs baseline: 2.4879x; 1.4525x over previous
#include <cuda_runtime.h>
#include <cuda_bf16.h>
#include <math.h>
#include <stdint.h>

#define BB 8
#define TT 769
#define CC 1024
#define HH 16
#define HD 64
#define LL 32
#define COND 256
#define MROWS (BB*TT)   // 6152

// ---------------------------------------------------------------------------
// Device scratch (allocation-free requirement -> globals)
// ---------------------------------------------------------------------------
__device__ float g_Q[(size_t)MROWS * CC];
__device__ float g_K[(size_t)MROWS * CC];
__device__ float g_V[(size_t)MROWS * CC];

__device__ __nv_bfloat16 g_xqh[(size_t)MROWS * CC], g_xql[(size_t)MROWS * CC];
__device__ __nv_bfloat16 g_xkh[(size_t)MROWS * CC], g_xkl[(size_t)MROWS * CC];
__device__ __nv_bfloat16 g_Wh[(size_t)4 * CC * CC], g_Wl[(size_t)4 * CC * CC];
__device__ __nv_bfloat16 g_qh[(size_t)MROWS * CC], g_ql[(size_t)MROWS * CC];
__device__ __nv_bfloat16 g_kh[(size_t)MROWS * CC], g_kl[(size_t)MROWS * CC];
__device__ __nv_bfloat16 g_vh[(size_t)MROWS * CC], g_vl[(size_t)MROWS * CC];
__device__ __nv_bfloat16 g_ah[(size_t)MROWS * CC], g_al[(size_t)MROWS * CC];

// ---------------------------------------------------------------------------
// Helpers
// ---------------------------------------------------------------------------
__device__ __forceinline__ uint32_t smem_to_u32(const void* p) {
    uint32_t a;
    asm("{ .reg .u64 t; cvta.to.shared.u64 t, %1; cvt.u32.u64 %0, t; }"
        : "=r"(a) : "l"(p));
    return a;
}
__device__ __forceinline__ void ldm_x4(uint32_t* r, uint32_t addr) {
    asm volatile("ldmatrix.sync.aligned.m8n8.x4.shared.b16 {%0,%1,%2,%3}, [%4];"
        : "=r"(r[0]), "=r"(r[1]), "=r"(r[2]), "=r"(r[3]) : "r"(addr));
}
__device__ __forceinline__ void ldm_x4_t(uint32_t* r, uint32_t addr) {
    asm volatile("ldmatrix.sync.aligned.m8n8.x4.trans.shared.b16 {%0,%1,%2,%3}, [%4];"
        : "=r"(r[0]), "=r"(r[1]), "=r"(r[2]), "=r"(r[3]) : "r"(addr));
}
__device__ __forceinline__ void mma16816(float* d, const uint32_t* a,
                                         uint32_t b0, uint32_t b1) {
    asm volatile(
        "mma.sync.aligned.m16n8k16.row.col.f32.bf16.bf16.f32 "
        "{%0,%1,%2,%3}, {%4,%5,%6,%7}, {%8,%9}, {%0,%1,%2,%3};"
        : "+f"(d[0]), "+f"(d[1]), "+f"(d[2]), "+f"(d[3])
        : "r"(a[0]), "r"(a[1]), "r"(a[2]), "r"(a[3]), "r"(b0), "r"(b1));
}
__device__ __forceinline__ void cp16(uint32_t dst, const void* src, bool pred) {
    int n = pred ? 16 : 0;
    asm volatile("cp.async.cg.shared.global [%0], [%1], 16, %2;"
        :: "r"(dst), "l"(src), "r"(n) : "memory");
}
#define CP_COMMIT() asm volatile("cp.async.commit_group;" ::: "memory")
#define CP_WAIT0()  asm volatile("cp.async.wait_group 0;" ::: "memory")
#define CP_WAIT1()  asm volatile("cp.async.wait_group 1;" ::: "memory")

// pack 2 floats -> bf16x2 hi + bf16x2 residual-lo
__device__ __forceinline__ void pack_split(float x, float y,
                                           uint32_t& hi, uint32_t& lo) {
    __nv_bfloat162 h = __floats2bfloat162_rn(x, y);
    float hx = __low2float(h), hy = __high2float(h);
    __nv_bfloat162 l2 = __floats2bfloat162_rn(x - hx, y - hy);
    hi = *reinterpret_cast<uint32_t*>(&h);
    lo = *reinterpret_cast<uint32_t*>(&l2);
}

// ---------------------------------------------------------------------------
// Split kernels (one-time f32 -> planar bf16 hi/lo)
// ---------------------------------------------------------------------------
__global__ void split_kernel(const float* __restrict__ src,
                             __nv_bfloat16* __restrict__ hi,
                             __nv_bfloat16* __restrict__ lo, int n4)
{
    int idx = blockIdx.x * blockDim.x + threadIdx.x;
    if (idx >= n4) return;
    float4 v = reinterpret_cast<const float4*>(src)[idx];
    uint2 h, l;
    pack_split(v.x, v.y, h.x, l.x);
    pack_split(v.z, v.w, h.y, l.y);
    reinterpret_cast<uint2*>(hi)[idx] = h;
    reinterpret_cast<uint2*>(lo)[idx] = l;
}

// rotary on first LL dims/head of q,k + fold 1/8 scale into q + split
__global__ void rotary_split_kernel(const float* __restrict__ Q,
                                    const float* __restrict__ K,
                                    const float* __restrict__ rope,
                                    __nv_bfloat16* __restrict__ qh,
                                    __nv_bfloat16* __restrict__ ql,
                                    __nv_bfloat16* __restrict__ kh,
                                    __nv_bfloat16* __restrict__ kl)
{
    int idx = blockIdx.x * blockDim.x + threadIdx.x;   // pair index
    const int NP = MROWS * (CC / 2);
    if (idx >= NP) return;
    int row = idx >> 9;
    int c = (idx & 511) * 2;
    int d = c & 63;
    int t = row % TT;
    size_t off = (size_t)row * CC + c;
    float2 qv = *reinterpret_cast<const float2*>(Q + off);
    float2 kv = *reinterpret_cast<const float2*>(K + off);
    if (d < LL) {
        float f0 = rope[t * LL + d], f1 = rope[t * LL + d + 1];
        float c0 = cosf(f0), s0 = sinf(f0);
        float c1 = cosf(f1), s1 = sinf(f1);
        float qx = qv.x, qy = qv.y, kx = kv.x, ky = kv.y;
        qv.x = qx * c0 - qy * s0;  qv.y = qy * c1 + qx * s1;
        kv.x = kx * c0 - ky * s0;  kv.y = ky * c1 + kx * s1;
    }
    qv.x *= 0.125f; qv.y *= 0.125f;     // fold softmax scale (exact)
    uint32_t h, l;
    pack_split(qv.x, qv.y, h, l);
    *reinterpret_cast<uint32_t*>(qh + off) = h;
    *reinterpret_cast<uint32_t*>(ql + off) = l;
    pack_split(kv.x, kv.y, h, l);
    *reinterpret_cast<uint32_t*>(kh + off) = h;
    *reinterpret_cast<uint32_t*>(kl + off) = l;
}

// ===========================================================================
// GEMM v2: Y[m,n] = sum_k A[m,k]*B[n,k] + bias[n], A/B pre-split bf16 hi/lo.
// 128x128x(32-chunk) tile, 8 warps (2Mx4N), cp.async double-buffered smem.
// 3-term split: AhBh + AhBl + AlBh. blockIdx.z picks one of 3 tuples.
// ===========================================================================
#define RSB 80                 // smem row stride (64B data + 16 pad)
#define GBUF 40960             // per-buffer bytes: 4 arrays x 128 x 80

__global__ void __launch_bounds__(256) gemm_tc_kernel(
    const __nv_bfloat16* __restrict__ A0h, const __nv_bfloat16* __restrict__ A0l,
    const __nv_bfloat16* __restrict__ B0h, const __nv_bfloat16* __restrict__ B0l,
    const float* __restrict__ b0, float* __restrict__ Y0,
    const __nv_bfloat16* __restrict__ A1h, const __nv_bfloat16* __restrict__ A1l,
    const __nv_bfloat16* __restrict__ B1h, const __nv_bfloat16* __restrict__ B1l,
    const float* __restrict__ b1, float* __restrict__ Y1,
    const __nv_bfloat16* __restrict__ A2h, const __nv_bfloat16* __restrict__ A2l,
    const __nv_bfloat16* __restrict__ B2h, const __nv_bfloat16* __restrict__ B2l,
    const float* __restrict__ b2, float* __restrict__ Y2,
    int M)
{
    extern __shared__ char sm[];
    const uint32_t smb = smem_to_u32(sm);
    const int tid = threadIdx.x;
    const int lid = tid & 31;
    const int wid = tid >> 5;
    const int wm = wid >> 2, wn = wid & 3;

    const __nv_bfloat16 *Ah, *Al, *Bh, *Bl;
    const float* Bi; float* Y;
    if (blockIdx.z == 0)      { Ah=A0h; Al=A0l; Bh=B0h; Bl=B0l; Bi=b0; Y=Y0; }
    else if (blockIdx.z == 1) { Ah=A1h; Al=A1l; Bh=B1h; Bl=B1l; Bi=b1; Y=Y1; }
    else                      { Ah=A2h; Al=A2l; Bh=B2h; Bl=B2l; Bi=b2; Y=Y2; }

    const int bm = blockIdx.y * 128, bn = blockIdx.x * 128;
    const uint32_t lmoff = (uint32_t)((lid & 15) * RSB + ((lid >> 4) << 4));

    // per-thread cp.async slots: 2 per array (512 slots = 128 rows x 4 segs)
    const int r0 = tid >> 2, s0 = (tid & 3);           // slot j=0
    const int r1 = (tid + 256) >> 2, s1 = ((tid + 256) & 3);

    float acc[4][4][4];
#pragma unroll
    for (int a = 0; a < 4; a++)
#pragma unroll
        for (int b = 0; b < 4; b++)
#pragma unroll
            for (int c = 0; c < 4; c++) acc[a][b][c] = 0.f;

    auto issue = [&](int ch, int buf) {
        uint32_t base = smb + buf * GBUF;
#pragma unroll
        for (int j = 0; j < 2; j++) {
            int row = j ? r1 : r0;
            int seg = j ? s1 : s0;
            uint32_t doff = (uint32_t)(row * RSB + seg * 16);
            bool ap = (bm + row) < M;
            size_t abyte = ((size_t)(bm + row) * CC + ch * 32) * 2 + seg * 16;
            size_t bbyte = ((size_t)(bn + row) * CC + ch * 32) * 2 + seg * 16;
            cp16(base + doff,             (const char*)Ah + abyte, ap);
            cp16(base + 10240 + doff,     (const char*)Al + abyte, ap);
            cp16(base + 20480 + doff,     (const char*)Bh + bbyte, true);
            cp16(base + 30720 + doff,     (const char*)Bl + bbyte, true);
        }
    };

    issue(0, 0);
    CP_COMMIT();

    for (int ch = 0; ch < 32; ch++) {
        if (ch < 31) { issue(ch + 1, (ch + 1) & 1); CP_COMMIT(); CP_WAIT1(); }
        else         { CP_WAIT0(); }
        __syncthreads();

        const uint32_t base = smb + (ch & 1) * GBUF;
#pragma unroll
        for (int ks = 0; ks < 2; ks++) {
            const uint32_t kofs = (uint32_t)(ks * 32);
            uint32_t Af[4][4], Al4[4][4], Bf[2][4];
#pragma unroll
            for (int mt = 0; mt < 4; mt++) {
                uint32_t rb = (uint32_t)((wm * 64 + mt * 16) * RSB) + kofs + lmoff;
                ldm_x4(Af[mt],  base + rb);
                ldm_x4(Al4[mt], base + 10240 + rb);
            }
#pragma unroll
            for (int np = 0; np < 2; np++) {
                uint32_t rb = (uint32_t)((wn * 32 + np * 16) * RSB) + kofs + lmoff;
                ldm_x4(Bf[np], base + 20480 + rb);
            }
#pragma unroll
            for (int mt = 0; mt < 4; mt++)
#pragma unroll
                for (int nt = 0; nt < 4; nt++) {
                    uint32_t bb0 = Bf[nt >> 1][nt & 1];
                    uint32_t bb1 = Bf[nt >> 1][2 + (nt & 1)];
                    mma16816(acc[mt][nt], Af[mt], bb0, bb1);
                    mma16816(acc[mt][nt], Al4[mt], bb0, bb1);
                }
#pragma unroll
            for (int np = 0; np < 2; np++) {
                uint32_t rb = (uint32_t)((wn * 32 + np * 16) * RSB) + kofs + lmoff;
                ldm_x4(Bf[np], base + 30720 + rb);
            }
#pragma unroll
            for (int mt = 0; mt < 4; mt++)
#pragma unroll
                for (int nt = 0; nt < 4; nt++) {
                    uint32_t bb0 = Bf[nt >> 1][nt & 1];
                    uint32_t bb1 = Bf[nt >> 1][2 + (nt & 1)];
                    mma16816(acc[mt][nt], Af[mt], bb0, bb1);
                }
        }
        __syncthreads();
    }

    const int rbase = bm + wm * 64 + (lid >> 2);
    const int cbase = bn + wn * 32 + (lid & 3) * 2;
#pragma unroll
    for (int mt = 0; mt < 4; mt++) {
#pragma unroll
        for (int nt = 0; nt < 4; nt++) {
            int c = cbase + nt * 8;
            float2 bv = *(const float2*)(Bi + c);
            int rr0 = rbase + mt * 16;
            int rr1 = rr0 + 8;
            if (rr0 < M)
                *(float2*)(Y + (size_t)rr0 * CC + c) =
                    make_float2(acc[mt][nt][0] + bv.x, acc[mt][nt][1] + bv.y);
            if (rr1 < M)
                *(float2*)(Y + (size_t)rr1 * CC + c) =
                    make_float2(acc[mt][nt][2] + bv.x, acc[mt][nt][3] + bv.y);
        }
    }
}

// ===========================================================================
// Tensor-core flash attention. CTA = (qtile 64, h, b); 4 warps x 16 q-rows.
// K: non-trans B operand (kv=n, hd=k). V: row-major, ldmatrix.x4.trans.
// 3-term splits for QK^T and PV. cp.async double-buffered KV tiles.
// Emits attention output pre-split (hi/lo bf16) for the out-projection.
// ===========================================================================
#define AST 144                 // attn smem row stride (128B data + 16 pad)
#define SQH 0
#define SQL 9216
#define SKH(b) (18432 + (b) * 18432)
#define SKL(b) (SKH(b) + 9216)
#define SVH(b) (55296 + (b) * 18432)
#define SVL(b) (SVH(b) + 9216)
#define SMEM_ATTN 92160

__global__ void __launch_bounds__(128) attn_tc_kernel(
    const __nv_bfloat16* __restrict__ qh, const __nv_bfloat16* __restrict__ ql,
    const __nv_bfloat16* __restrict__ kh, const __nv_bfloat16* __restrict__ kl,
    const __nv_bfloat16* __restrict__ vh, const __nv_bfloat16* __restrict__ vl,
    __nv_bfloat16* __restrict__ oh, __nv_bfloat16* __restrict__ ol)
{
    extern __shared__ char sm[];
    const uint32_t smb = smem_to_u32(sm);
    const int tid = threadIdx.x;
    const int l = tid & 31, w = tid >> 5;
    const int q0 = blockIdx.x * 64;
    const int h = blockIdx.y, b = blockIdx.z;
    const size_t rb = (size_t)b * TT * CC + (size_t)h * HD;  // elem offset, row 0

    // ---- issue Q (once) ----
#pragma unroll
    for (int j = 0; j < 4; j++) {
        int slot = tid + j * 128;
        int row = slot >> 3, seg = slot & 7;
        bool p = (q0 + row) < TT;
        size_t byte = (rb + (size_t)(q0 + row) * CC) * 2 + seg * 16;
        uint32_t doff = (uint32_t)(row * AST + seg * 16);
        cp16(smb + SQH + doff, (const char*)qh + byte, p);
        cp16(smb + SQL + doff, (const char*)ql + byte, p);
    }

    auto issue_kv = [&](int t, int buf) {
        int kv0 = t * 64;
#pragma unroll
        for (int j = 0; j < 4; j++) {
            int slot = tid + j * 128;
            int row = slot >> 3, seg = slot & 7;
            bool p = (kv0 + row) < TT;
            size_t byte = (rb + (size_t)(kv0 + row) * CC) * 2 + seg * 16;
            uint32_t doff = (uint32_t)(row * AST + seg * 16);
            cp16(smb + SKH(buf) + doff, (const char*)kh + byte, p);
            cp16(smb + SKL(buf) + doff, (const char*)kl + byte, p);
            cp16(smb + SVH(buf) + doff, (const char*)vh + byte, p);
            cp16(smb + SVL(buf) + doff, (const char*)vl + byte, p);
        }
    };

    issue_kv(0, 0);
    CP_COMMIT();

    int kv_end = q0 + COND + 63;
    if (kv_end > TT) kv_end = TT;
    const int nkv = (kv_end + 63) >> 6;

    const uint32_t lmoff = (uint32_t)((l & 15) * AST + ((l >> 4) << 4));
    const int qg0 = q0 + w * 16 + (l >> 2);
    const int qg1 = qg0 + 8;

    uint32_t Qf[4][4], Ql4[4][4];
    float Oacc[8][4];
#pragma unroll
    for (int i = 0; i < 8; i++)
#pragma unroll
        for (int j = 0; j < 4; j++) Oacc[i][j] = 0.f;
    float m0 = -1e30f, m1 = -1e30f, l0 = 0.f, l1 = 0.f;

    for (int t = 0; t < nkv; t++) {
        const int buf = t & 1;
        if (t + 1 < nkv) { issue_kv(t + 1, buf ^ 1); CP_COMMIT(); CP_WAIT1(); }
        else             { CP_WAIT0(); }
        __syncthreads();

        if (t == 0) {
            // load Q fragments (scale already folded in)
#pragma unroll
            for (int ks = 0; ks < 4; ks++) {
                uint32_t rbq = (uint32_t)((w * 16) * AST) + ks * 32 + lmoff;
                ldm_x4(Qf[ks],  smb + SQH + rbq);
                ldm_x4(Ql4[ks], smb + SQL + rbq);
            }
        }

        const int kv0 = t * 64;
        float S[8][4];
#pragma unroll
        for (int i = 0; i < 8; i++)
#pragma unroll
            for (int j = 0; j < 4; j++) S[i][j] = 0.f;

        // ---- S = Q K^T (3-term split) ----
#pragma unroll
        for (int ks = 0; ks < 4; ks++) {
            uint32_t Kf[4][4], Kl4[4][4];
#pragma unroll
            for (int np = 0; np < 4; np++) {
                uint32_t rbk = (uint32_t)((np * 16) * AST) + ks * 32 + lmoff;
                ldm_x4(Kf[np],  smb + SKH(buf) + rbk);
                ldm_x4(Kl4[np], smb + SKL(buf) + rbk);
            }
#pragma unroll
            for (int nt = 0; nt < 8; nt++) {
                uint32_t bh0 = Kf[nt >> 1][nt & 1];
                uint32_t bh1 = Kf[nt >> 1][2 + (nt & 1)];
                mma16816(S[nt], Qf[ks], bh0, bh1);
                mma16816(S[nt], Ql4[ks], bh0, bh1);
                uint32_t bl0 = Kl4[nt >> 1][nt & 1];
                uint32_t bl1 = Kl4[nt >> 1][2 + (nt & 1)];
                mma16816(S[nt], Qf[ks], bl0, bl1);
            }
        }

        // ---- mask + online softmax ----
        float mx0 = -1e30f, mx1 = -1e30f;
#pragma unroll
        for (int nt = 0; nt < 8; nt++) {
#pragma unroll
            for (int e = 0; e < 2; e++) {
                int kvc = kv0 + nt * 8 + (l & 3) * 2 + e;
                bool inb = kvc < TT;
                if (!(inb && kvc < COND + qg0)) S[nt][e] = -1e30f;
                if (!(inb && kvc < COND + qg1)) S[nt][2 + e] = -1e30f;
                mx0 = fmaxf(mx0, S[nt][e]);
                mx1 = fmaxf(mx1, S[nt][2 + e]);
            }
        }
        mx0 = fmaxf(mx0, __shfl_xor_sync(0xffffffffu, mx0, 1));
        mx0 = fmaxf(mx0, __shfl_xor_sync(0xffffffffu, mx0, 2));
        mx1 = fmaxf(mx1, __shfl_xor_sync(0xffffffffu, mx1, 1));
        mx1 = fmaxf(mx1, __shfl_xor_sync(0xffffffffu, mx1, 2));

        float mn0 = fmaxf(m0, mx0), mn1 = fmaxf(m1, mx1);
        float al0 = __expf(m0 - mn0), al1 = __expf(m1 - mn1);
        m0 = mn0; m1 = mn1;

        float s0 = 0.f, s1 = 0.f;
#pragma unroll
        for (int nt = 0; nt < 8; nt++) {
#pragma unroll
            for (int e = 0; e < 2; e++) {
                S[nt][e] = __expf(S[nt][e] - mn0);         s0 += S[nt][e];
                S[nt][2 + e] = __expf(S[nt][2 + e] - mn1); s1 += S[nt][2 + e];
            }
        }
        s0 += __shfl_xor_sync(0xffffffffu, s0, 1);
        s0 += __shfl_xor_sync(0xffffffffu, s0, 2);
        s1 += __shfl_xor_sync(0xffffffffu, s1, 1);
        s1 += __shfl_xor_sync(0xffffffffu, s1, 2);
        l0 = l0 * al0 + s0;
        l1 = l1 * al1 + s1;

#pragma unroll
        for (int nt = 0; nt < 8; nt++) {
            Oacc[nt][0] *= al0; Oacc[nt][1] *= al0;
            Oacc[nt][2] *= al1; Oacc[nt][3] *= al1;
        }

        // ---- O += P V (3-term split) ----
#pragma unroll
        for (int ks = 0; ks < 4; ks++) {
            uint32_t Ph[4], Pl[4];
            pack_split(S[2 * ks][0],     S[2 * ks][1],     Ph[0], Pl[0]);
            pack_split(S[2 * ks][2],     S[2 * ks][3],     Ph[1], Pl[1]);
            pack_split(S[2 * ks + 1][0], S[2 * ks + 1][1], Ph[2], Pl[2]);
            pack_split(S[2 * ks + 1][2], S[2 * ks + 1][3], Ph[3], Pl[3]);

            uint32_t Vf[4][4], Vl4[4][4];
#pragma unroll
            for (int np = 0; np < 4; np++) {
                uint32_t rbv = (uint32_t)((ks * 16) * AST) + np * 32 + lmoff;
                ldm_x4_t(Vf[np],  smb + SVH(buf) + rbv);
                ldm_x4_t(Vl4[np], smb + SVL(buf) + rbv);
            }
#pragma unroll
            for (int nt = 0; nt < 8; nt++) {
                uint32_t bh0 = Vf[nt >> 1][(nt & 1) * 2];
                uint32_t bh1 = Vf[nt >> 1][(nt & 1) * 2 + 1];
                mma16816(Oacc[nt], Ph, bh0, bh1);
                mma16816(Oacc[nt], Pl, bh0, bh1);
                uint32_t bl0 = Vl4[nt >> 1][(nt & 1) * 2];
                uint32_t bl1 = Vl4[nt >> 1][(nt & 1) * 2 + 1];
                mma16816(Oacc[nt], Ph, bl0, bl1);
            }
        }
        __syncthreads();
    }

    // ---- normalize + store split output ----
    float inv0 = 1.f / l0, inv1 = 1.f / l1;
#pragma unroll
    for (int nt = 0; nt < 8; nt++) {
        int c = nt * 8 + (l & 3) * 2;
        uint32_t hi, lo;
        if (qg0 < TT) {
            pack_split(Oacc[nt][0] * inv0, Oacc[nt][1] * inv0, hi, lo);
            size_t off = rb + (size_t)qg0 * CC + c;
            *reinterpret_cast<uint32_t*>(oh + off) = hi;
            *reinterpret_cast<uint32_t*>(ol + off) = lo;
        }
        if (qg1 < TT) {
            pack_split(Oacc[nt][2] * inv1, Oacc[nt][3] * inv1, hi, lo);
            size_t off = rb + (size_t)qg1 * CC + c;
            *reinterpret_cast<uint32_t*>(oh + off) = hi;
            *reinterpret_cast<uint32_t*>(ol + off) = lo;
        }
    }
}

// ---------------------------------------------------------------------------
// Launch
// ---------------------------------------------------------------------------
extern "C" void kernel_launch(void* const* d_in, const int* in_sizes, int n_in,
                              void* d_out, int out_size)
{
    const float* x_q  = (const float*)d_in[0];
    const float* x_kv = (const float*)d_in[1];
    const float* rope = (const float*)d_in[2];
    const float* Wq   = (const float*)d_in[3];
    const float* bq   = (const float*)d_in[4];
    const float* Wk   = (const float*)d_in[5];
    const float* bk   = (const float*)d_in[6];
    const float* Wv   = (const float*)d_in[7];
    const float* bv   = (const float*)d_in[8];
    const float* Wp   = (const float*)d_in[9];
    const float* bp   = (const float*)d_in[10];
    float* out = (float*)d_out;

    float *q, *k, *v;
    cudaGetSymbolAddress((void**)&q, g_Q);
    cudaGetSymbolAddress((void**)&k, g_K);
    cudaGetSymbolAddress((void**)&v, g_V);
    __nv_bfloat16 *xqh, *xql, *xkh, *xkl, *Wh, *Wl;
    __nv_bfloat16 *qh, *ql, *kh, *kl, *vh, *vl, *ah, *al;
    cudaGetSymbolAddress((void**)&xqh, g_xqh);
    cudaGetSymbolAddress((void**)&xql, g_xql);
    cudaGetSymbolAddress((void**)&xkh, g_xkh);
    cudaGetSymbolAddress((void**)&xkl, g_xkl);
    cudaGetSymbolAddress((void**)&Wh,  g_Wh);
    cudaGetSymbolAddress((void**)&Wl,  g_Wl);
    cudaGetSymbolAddress((void**)&qh,  g_qh);
    cudaGetSymbolAddress((void**)&ql,  g_ql);
    cudaGetSymbolAddress((void**)&kh,  g_kh);
    cudaGetSymbolAddress((void**)&kl,  g_kl);
    cudaGetSymbolAddress((void**)&vh,  g_vh);
    cudaGetSymbolAddress((void**)&vl,  g_vl);
    cudaGetSymbolAddress((void**)&ah,  g_ah);
    cudaGetSymbolAddress((void**)&al,  g_al);

    cudaFuncSetAttribute(gemm_tc_kernel,
        cudaFuncAttributeMaxDynamicSharedMemorySize, 2 * GBUF);
    cudaFuncSetAttribute(attn_tc_kernel,
        cudaFuncAttributeMaxDynamicSharedMemorySize, SMEM_ATTN);

    // 1) one-time splits of inputs and weights
    const int NX4 = MROWS * CC / 4;        // 1,574,912
    const int NW4 = CC * CC / 4;           //   262,144
    split_kernel<<<(NX4 + 255) / 256, 256>>>(x_q,  xqh, xql, NX4);
    split_kernel<<<(NX4 + 255) / 256, 256>>>(x_kv, xkh, xkl, NX4);
    split_kernel<<<(NW4 + 255) / 256, 256>>>(Wq, Wh,              Wl,              NW4);
    split_kernel<<<(NW4 + 255) / 256, 256>>>(Wk, Wh + CC * CC,     Wl + CC * CC,     NW4);
    split_kernel<<<(NW4 + 255) / 256, 256>>>(Wv, Wh + 2 * CC * CC, Wl + 2 * CC * CC, NW4);
    split_kernel<<<(NW4 + 255) / 256, 256>>>(Wp, Wh + 3 * CC * CC, Wl + 3 * CC * CC, NW4);

    // 2) fused Q/K/V projections (f32 out)
    dim3 g_qkv(CC / 128, (MROWS + 127) / 128, 3);   // (8, 49, 3)
    gemm_tc_kernel<<<g_qkv, 256, 2 * GBUF>>>(
        xqh, xql, Wh,              Wl,              bq, q,
        xkh, xkl, Wh + CC * CC,     Wl + CC * CC,     bk, k,
        xkh, xkl, Wh + 2 * CC * CC, Wl + 2 * CC * CC, bv, v, MROWS);

    // 3) rotary + scale-fold + split q,k ; split v
    const int NPR = MROWS * (CC / 2);
    rotary_split_kernel<<<(NPR + 255) / 256, 256>>>(q, k, rope, qh, ql, kh, kl);
    split_kernel<<<(NX4 + 255) / 256, 256>>>(v, vh, vl, NX4);

    // 4) tensor-core attention -> split output
    dim3 attn_grid((TT + 63) / 64, HH, BB);          // (13, 16, 8)
    attn_tc_kernel<<<attn_grid, 128, SMEM_ATTN>>>(qh, ql, kh, kl, vh, vl, ah, al);

    // 5) output projection
    dim3 g_out(CC / 128, (MROWS + 127) / 128, 1);
    gemm_tc_kernel<<<g_out, 256, 2 * GBUF>>>(
        ah, al, Wh + 3 * CC * CC, Wl + 3 * CC * CC, bp, out,
        ah, al, Wh + 3 * CC * CC, Wl + 3 * CC * CC, bp, out,
        ah, al, Wh + 3 * CC * CC, Wl + 3 * CC * CC, bp, out, MROWS);
}